// round 14
// baseline (speedup 1.0000x reference)
#include <cuda_runtime.h>
#include <cuda_bf16.h>
#include <math.h>
#include <stdint.h>

// ---------------------------------------------------------------------------
// Problem constants
// ---------------------------------------------------------------------------
#define FEAT     128
#define FEAT3    384
#define NRBF     20
#define MAXNODES 20000

__device__ float g_h  [MAXNODES * FEAT];
__device__ float g_inv[MAXNODES * FEAT3];
__device__ int   g_nbrs_is64;   // 1 if nbrs buffer is int64, 0 if int32

// ---------------------------------------------------------------------------
// packed f32x2 helpers (edge kernel)
// ---------------------------------------------------------------------------
__device__ __forceinline__ void fma2(unsigned long long &acc,
                                     unsigned long long a,
                                     unsigned long long b) {
    asm("fma.rn.f32x2 %0, %1, %2, %0;" : "+l"(acc) : "l"(a), "l"(b));
}
__device__ __forceinline__ unsigned long long pack2(float x, float y) {
    unsigned long long p;
    asm("mov.b64 %0, {%1, %2};" : "=l"(p) : "f"(x), "f"(y));
    return p;
}
__device__ __forceinline__ void unpack2(unsigned long long p, float &x, float &y) {
    asm("mov.b64 {%0, %1}, %2;" : "=f"(x), "=f"(y) : "l"(p));
}

// ---------------------------------------------------------------------------
// nbrs dtype detector (int64 layout has all-zero odd u32 words)
// ---------------------------------------------------------------------------
__global__ void detect_nbrs_kernel(const unsigned int* __restrict__ p, int n_words)
{
    if (threadIdx.x == 0 && blockIdx.x == 0) {
        unsigned int acc = 0;
        int lim = n_words < 512 ? n_words : 512;
        for (int i = 1; i < lim; i += 2) acc |= p[i];
        g_nbrs_is64 = (acc == 0u) ? 1 : 0;
    }
}

// ---------------------------------------------------------------------------
// Split-bf16 tensor-core GEMM: C = act(A@B + bias), A[M,K] B[K,N] fp32.
// a = hi + lo (bf16 each); acc = Ahi*Bhi + Ahi*Blo + Alo*Bhi (fp32 MMA acc)
// -> rel err ~2^-16. CTA 128 thr, tile 64x64; warp tile 32x32 (2x m16, 4x n8),
// mma.sync.m16n8k16.row.col. K assumed multiple of 16, N multiple of 64.
// ---------------------------------------------------------------------------
__device__ __forceinline__ uint32_t pack_bf(float x, float y) {
    __nv_bfloat162 h = __floats2bfloat162_rn(x, y);
    return *reinterpret_cast<uint32_t*>(&h);
}
__device__ __forceinline__ void split_bf(float a, __nv_bfloat16 &hi, __nv_bfloat16 &lo) {
    hi = __float2bfloat16_rn(a);
    lo = __float2bfloat16_rn(a - __bfloat162float(hi));
}
__device__ __forceinline__ void mma_bf16(float* c, const uint32_t* a, const uint32_t* b) {
    asm volatile(
        "mma.sync.aligned.m16n8k16.row.col.f32.bf16.bf16.f32 "
        "{%0,%1,%2,%3}, {%4,%5,%6,%7}, {%8,%9}, {%0,%1,%2,%3};"
        : "+f"(c[0]), "+f"(c[1]), "+f"(c[2]), "+f"(c[3])
        : "r"(a[0]), "r"(a[1]), "r"(a[2]), "r"(a[3]), "r"(b[0]), "r"(b[1]));
}

__global__ __launch_bounds__(128) void hgemm_kernel(
    const float* __restrict__ A, const float* __restrict__ B,
    const float* __restrict__ bias, float* __restrict__ C,
    int M, int N, int K, int act)
{
    // A tiles row-major [m][k]; B tiles stored TRANSPOSED [n][k]
    __shared__ __nv_bfloat16 Ah[64][16], Al[64][16];
    __shared__ __nv_bfloat16 Bh[64][16], Bl[64][16];

    const int tid  = threadIdx.x;
    const int warp = tid >> 5;
    const int l    = tid & 31;
    const int gr   = l >> 2;          // group row 0..7
    const int tg   = l & 3;           // thread-in-group 0..3
    const int wm   = (warp >> 1) * 32;  // warp m offset in CTA tile
    const int wn   = (warp & 1) * 32;   // warp n offset
    const int row0 = blockIdx.x * 64;
    const int col0 = blockIdx.y * 64;

    float acc[2][4][4];
    #pragma unroll
    for (int t = 0; t < 2; t++)
        #pragma unroll
        for (int u = 0; u < 4; u++)
            #pragma unroll
            for (int v = 0; v < 4; v++) acc[t][u][v] = 0.0f;

    for (int kk = 0; kk < K; kk += 16) {
        // ---- stage A 64x16 (256 float4; 2 per thread), split hi/lo ----
        #pragma unroll
        for (int s = 0; s < 2; s++) {
            int f  = tid + s * 128;
            int r  = f >> 2;
            int kq = (f & 3) * 4;
            float4 v = make_float4(0.f, 0.f, 0.f, 0.f);
            if (row0 + r < M)
                v = *(const float4*)&A[(size_t)(row0 + r) * K + kk + kq];
            __nv_bfloat16 h0,l0,h1,l1,h2,l2,h3,l3;
            split_bf(v.x, h0, l0); split_bf(v.y, h1, l1);
            split_bf(v.z, h2, l2); split_bf(v.w, h3, l3);
            Ah[r][kq+0]=h0; Ah[r][kq+1]=h1; Ah[r][kq+2]=h2; Ah[r][kq+3]=h3;
            Al[r][kq+0]=l0; Al[r][kq+1]=l1; Al[r][kq+2]=l2; Al[r][kq+3]=l3;
        }
        // ---- stage B 16x64 -> transposed [n][k], split hi/lo ----
        #pragma unroll
        for (int s = 0; s < 2; s++) {
            int f  = tid + s * 128;
            int kr = f >> 4;
            int nq = (f & 15) * 4;
            float4 v = *(const float4*)&B[(size_t)(kk + kr) * N + col0 + nq];
            __nv_bfloat16 h0,l0,h1,l1,h2,l2,h3,l3;
            split_bf(v.x, h0, l0); split_bf(v.y, h1, l1);
            split_bf(v.z, h2, l2); split_bf(v.w, h3, l3);
            Bh[nq+0][kr]=h0; Bh[nq+1][kr]=h1; Bh[nq+2][kr]=h2; Bh[nq+3][kr]=h3;
            Bl[nq+0][kr]=l0; Bl[nq+1][kr]=l1; Bl[nq+2][kr]=l2; Bl[nq+3][kr]=l3;
        }
        __syncthreads();

        // ---- fragments ----
        uint32_t ah[2][4], al[2][4], bh[4][2], bl[4][2];
        #pragma unroll
        for (int t = 0; t < 2; t++) {
            int r1 = wm + t * 16 + gr;
            ah[t][0] = *(const uint32_t*)&Ah[r1    ][tg * 2    ];
            ah[t][1] = *(const uint32_t*)&Ah[r1 + 8][tg * 2    ];
            ah[t][2] = *(const uint32_t*)&Ah[r1    ][tg * 2 + 8];
            ah[t][3] = *(const uint32_t*)&Ah[r1 + 8][tg * 2 + 8];
            al[t][0] = *(const uint32_t*)&Al[r1    ][tg * 2    ];
            al[t][1] = *(const uint32_t*)&Al[r1 + 8][tg * 2    ];
            al[t][2] = *(const uint32_t*)&Al[r1    ][tg * 2 + 8];
            al[t][3] = *(const uint32_t*)&Al[r1 + 8][tg * 2 + 8];
        }
        #pragma unroll
        for (int u = 0; u < 4; u++) {
            int n1 = wn + u * 8 + gr;
            bh[u][0] = *(const uint32_t*)&Bh[n1][tg * 2    ];
            bh[u][1] = *(const uint32_t*)&Bh[n1][tg * 2 + 8];
            bl[u][0] = *(const uint32_t*)&Bl[n1][tg * 2    ];
            bl[u][1] = *(const uint32_t*)&Bl[n1][tg * 2 + 8];
        }
        #pragma unroll
        for (int t = 0; t < 2; t++)
            #pragma unroll
            for (int u = 0; u < 4; u++) {
                mma_bf16(acc[t][u], ah[t], bh[u]);
                mma_bf16(acc[t][u], ah[t], bl[u]);
                mma_bf16(acc[t][u], al[t], bh[u]);
            }
        __syncthreads();
    }

    // ---- epilogue: bias + optional silu ----
    #pragma unroll
    for (int t = 0; t < 2; t++) {
        #pragma unroll
        for (int u = 0; u < 4; u++) {
            int colg = col0 + wn + u * 8 + tg * 2;
            float b0 = bias[colg], b1 = bias[colg + 1];
            #pragma unroll
            for (int half = 0; half < 2; half++) {
                int rowg = row0 + wm + t * 16 + gr + half * 8;
                if (rowg >= M) continue;
                float x0 = acc[t][u][half * 2 + 0] + b0;
                float x1 = acc[t][u][half * 2 + 1] + b1;
                if (act) {
                    x0 = x0 / (1.0f + expf(-x0));
                    x1 = x1 / (1.0f + expf(-x1));
                }
                *(float2*)&C[(size_t)rowg * N + colg] = make_float2(x0, x1);
            }
        }
    }
}

// ---------------------------------------------------------------------------
// Edge kernel (R4/R7/R12 exact — measured 172.7us, 72 regs, 4 CTAs/SM):
// out[e, c] = inv[j_e, c] * ((rbf_e @ Wr)[c]*env/d + br[c]*env)
// ---------------------------------------------------------------------------
#define ETILE 192

__global__ __launch_bounds__(192) void edge_kernel(
    const float* __restrict__ dist,
    const int* __restrict__ nb,         // raw u32 words of nbrs
    const float* __restrict__ Wr,
    const float* __restrict__ br,
    const float* __restrict__ inv,
    float* __restrict__ out,
    int n_edges)
{
    __shared__ __align__(16) float  sm_s[ETILE][NRBF];  // sines
    __shared__ __align__(16) float4 sm_meta[ETILE];     // (k1, k2, j_bits, -)

    const int t  = threadIdx.x;
    const int c0 = t * 2;
    const int is64 = g_nbrs_is64;

    unsigned long long wrA[NRBF / 2];
    unsigned long long wrB[NRBF / 2];
    #pragma unroll
    for (int m = 0; m < NRBF / 2; m++) {
        float2 we = *(const float2*)&Wr[(2 * m)     * FEAT3 + c0];
        float2 wo = *(const float2*)&Wr[(2 * m + 1) * FEAT3 + c0];
        wrA[m] = pack2(we.x, wo.x);
        wrB[m] = pack2(we.y, wo.y);
    }
    const float2 brp = *(const float2*)&br[c0];

    const int base = blockIdx.x * ETILE;
    const int cnt  = min(ETILE, n_edges - base);

    if (t < cnt) {
        const int e = base + t;
        const float d  = dist[e];
        const float th = d * 0.6283185307179586f;     // pi/5
        const float s1 = sinf(th);
        const float c1 = cosf(th);
        const float env = (d < 5.0f) ? 0.5f * (c1 + 1.0f) : 0.0f;
        const int   j   = is64 ? nb[4 * (long long)e + 2] : nb[2 * (long long)e + 1];
        sm_meta[t] = make_float4(env / d, env, __int_as_float(j), 0.0f);
        const float u = 2.0f * c1;
        float s[NRBF];
        float sp = 0.0f, sc = s1;
        #pragma unroll
        for (int n = 0; n < NRBF; n++) {
            s[n] = sc;
            float sn = fmaf(u, sc, -sp);
            sp = sc; sc = sn;
        }
        #pragma unroll
        for (int q = 0; q < NRBF / 4; q++)
            *(float4*)&sm_s[t][4 * q] =
                make_float4(s[4 * q], s[4 * q + 1], s[4 * q + 2], s[4 * q + 3]);
    }
    __syncthreads();

    float4 meta = sm_meta[0];
    float2 ph   = *(const float2*)&inv[(size_t)__float_as_int(meta.z) * FEAT3 + c0];

    for (int i = 0; i < cnt; i++) {
        const int inext = (i + 1 < cnt) ? (i + 1) : i;
        float4 meta_n = sm_meta[inext];
        float2 ph_n   = *(const float2*)&inv[(size_t)__float_as_int(meta_n.z) * FEAT3 + c0];

        const ulonglong2* sr = (const ulonglong2*)sm_s[i];

        unsigned long long a0e = 0ull, a0o = 0ull, a1e = 0ull, a1o = 0ull;
        #pragma unroll
        for (int q = 0; q < NRBF / 4; q++) {
            ulonglong2 sv = sr[q];
            fma2(a0e, sv.x, wrA[2 * q]);
            fma2(a1e, sv.x, wrB[2 * q]);
            fma2(a0o, sv.y, wrA[2 * q + 1]);
            fma2(a1o, sv.y, wrB[2 * q + 1]);
        }
        float xe0, xo0, xe1, xo1, ye0, yo0, ye1, yo1;
        unpack2(a0e, xe0, xo0); unpack2(a0o, xe1, xo1);
        unpack2(a1e, ye0, yo0); unpack2(a1o, ye1, yo1);
        const float dx = (xe0 + xo0) + (xe1 + xo1);
        const float dy = (ye0 + yo0) + (ye1 + yo1);

        const float wx = fmaf(dx, meta.x, brp.x * meta.y);
        const float wy = fmaf(dy, meta.x, brp.y * meta.y);
        float2 o = make_float2(wx * ph.x, wy * ph.y);
        *(float2*)&out[(size_t)(base + i) * FEAT3 + c0] = o;

        meta = meta_n;
        ph   = ph_n;
    }
}

// ---------------------------------------------------------------------------
// kernel_launch
// ---------------------------------------------------------------------------
extern "C" void kernel_launch(void* const* d_in, const int* in_sizes, int n_in,
                              void* d_out, int out_size)
{
    const float* s_j  = (const float*)d_in[0];
    const float* dist = (const float*)d_in[1];
    const int*   nb   = (const int*)  d_in[2];
    const float* W1   = (const float*)d_in[3];
    const float* b1   = (const float*)d_in[4];
    const float* W2   = (const float*)d_in[5];
    const float* b2   = (const float*)d_in[6];
    const float* Wr   = (const float*)d_in[7];
    const float* br   = (const float*)d_in[8];
    float*       out  = (float*)d_out;

    const int n_nodes = in_sizes[0] / FEAT;
    const int n_edges = in_sizes[1];

    float* hbuf;
    float* invbuf;
    cudaGetSymbolAddress((void**)&hbuf,   g_h);
    cudaGetSymbolAddress((void**)&invbuf, g_inv);

    detect_nbrs_kernel<<<1, 32>>>((const unsigned int*)nb, in_sizes[2]);

    // GEMM1: h = silu(s_j @ W1 + b1)   [tensor cores, split-bf16]
    {
        dim3 grid((n_nodes + 63) / 64, FEAT / 64);
        hgemm_kernel<<<grid, 128>>>(s_j, W1, b1, hbuf,
                                    n_nodes, FEAT, FEAT, /*act=*/1);
    }
    // GEMM2: inv = h @ W2 + b2         [tensor cores, split-bf16]
    {
        dim3 grid((n_nodes + 63) / 64, FEAT3 / 64);
        hgemm_kernel<<<grid, 128>>>(hbuf, W2, b2, invbuf,
                                    n_nodes, FEAT3, FEAT, /*act=*/0);
    }
    // Edge kernel (unchanged, measured)
    {
        dim3 grid((n_edges + ETILE - 1) / ETILE);
        edge_kernel<<<grid, ETILE>>>(dist, nb, Wr, br, invbuf, out, n_edges);
    }
}

// round 15
// speedup vs baseline: 1.2998x; 1.2998x over previous
#include <cuda_runtime.h>
#include <cuda_bf16.h>
#include <math.h>
#include <stdint.h>

// ---------------------------------------------------------------------------
// Problem constants
// ---------------------------------------------------------------------------
#define FEAT     128
#define FEAT3    384
#define NRBF     20
#define MAXNODES 20000
#define GK       128     // K of both node GEMMs

// split bf16 operand buffers
__device__ __nv_bfloat16 g_sh[MAXNODES * FEAT];   // s_j hi
__device__ __nv_bfloat16 g_sl[MAXNODES * FEAT];   // s_j lo
__device__ __nv_bfloat16 g_hh[MAXNODES * FEAT];   // h hi
__device__ __nv_bfloat16 g_hl[MAXNODES * FEAT];   // h lo
__device__ __nv_bfloat16 g_w1h[FEAT  * FEAT];     // W1^T hi  [n][k]
__device__ __nv_bfloat16 g_w1l[FEAT  * FEAT];
__device__ __nv_bfloat16 g_w2h[FEAT3 * FEAT];     // W2^T hi  [n][k]
__device__ __nv_bfloat16 g_w2l[FEAT3 * FEAT];
__device__ float g_inv[MAXNODES * FEAT3];
__device__ int   g_nbrs_is64;

// ---------------------------------------------------------------------------
// helpers
// ---------------------------------------------------------------------------
__device__ __forceinline__ void fma2(unsigned long long &acc,
                                     unsigned long long a,
                                     unsigned long long b) {
    asm("fma.rn.f32x2 %0, %1, %2, %0;" : "+l"(acc) : "l"(a), "l"(b));
}
__device__ __forceinline__ unsigned long long pack2(float x, float y) {
    unsigned long long p;
    asm("mov.b64 %0, {%1, %2};" : "=l"(p) : "f"(x), "f"(y));
    return p;
}
__device__ __forceinline__ void unpack2(unsigned long long p, float &x, float &y) {
    asm("mov.b64 {%0, %1}, %2;" : "=f"(x), "=f"(y) : "l"(p));
}
__device__ __forceinline__ void split_bf(float a, __nv_bfloat16 &hi, __nv_bfloat16 &lo) {
    hi = __float2bfloat16_rn(a);
    lo = __float2bfloat16_rn(a - __bfloat162float(hi));
}
__device__ __forceinline__ void mma_bf16(float* c, const uint32_t* a, const uint32_t* b) {
    asm volatile(
        "mma.sync.aligned.m16n8k16.row.col.f32.bf16.bf16.f32 "
        "{%0,%1,%2,%3}, {%4,%5,%6,%7}, {%8,%9}, {%0,%1,%2,%3};"
        : "+f"(c[0]), "+f"(c[1]), "+f"(c[2]), "+f"(c[3])
        : "r"(a[0]), "r"(a[1]), "r"(a[2]), "r"(a[3]), "r"(b[0]), "r"(b[1]));
}

// ---------------------------------------------------------------------------
// nbrs dtype detector
// ---------------------------------------------------------------------------
__global__ void detect_nbrs_kernel(const unsigned int* __restrict__ p, int n_words)
{
    if (threadIdx.x == 0 && blockIdx.x == 0) {
        unsigned int acc = 0;
        int lim = n_words < 512 ? n_words : 512;
        for (int i = 1; i < lim; i += 2) acc |= p[i];
        g_nbrs_is64 = (acc == 0u) ? 1 : 0;
    }
}

// ---------------------------------------------------------------------------
// split fp32 -> bf16 hi/lo (vectorized, [m][k] layout preserved)
// ---------------------------------------------------------------------------
__global__ void split_f32_kernel(const float4* __restrict__ in,
                                 __nv_bfloat16* __restrict__ hi,
                                 __nv_bfloat16* __restrict__ lo, int n4)
{
    int i = blockIdx.x * blockDim.x + threadIdx.x;
    if (i >= n4) return;
    float4 v = in[i];
    __nv_bfloat16 h0,l0,h1,l1,h2,l2,h3,l3;
    split_bf(v.x, h0, l0); split_bf(v.y, h1, l1);
    split_bf(v.z, h2, l2); split_bf(v.w, h3, l3);
    *(__nv_bfloat162*)&hi[i*4    ] = __nv_bfloat162(h0, h1);
    *(__nv_bfloat162*)&hi[i*4 + 2] = __nv_bfloat162(h2, h3);
    *(__nv_bfloat162*)&lo[i*4    ] = __nv_bfloat162(l0, l1);
    *(__nv_bfloat162*)&lo[i*4 + 2] = __nv_bfloat162(l2, l3);
}

// split + transpose both weight matrices: W[k][n] -> Wt[n][k] (hi/lo)
__global__ void split_w_kernel(const float* __restrict__ W1,
                               const float* __restrict__ W2)
{
    int idx = blockIdx.x * blockDim.x + threadIdx.x;
    if (idx < FEAT * FEAT) {
        int n = idx / FEAT, k = idx % FEAT;
        __nv_bfloat16 h, l;
        split_bf(W1[k * FEAT + n], h, l);
        g_w1h[n * FEAT + k] = h;
        g_w1l[n * FEAT + k] = l;
    }
    int i2 = idx - FEAT * FEAT;
    if (i2 >= 0 && i2 < FEAT3 * FEAT) {
        int n = i2 / FEAT, k = i2 % FEAT;
        __nv_bfloat16 h, l;
        split_bf(W2[k * FEAT3 + n], h, l);
        g_w2h[n * FEAT + k] = h;
        g_w2l[n * FEAT + k] = l;
    }
}

// ---------------------------------------------------------------------------
// Tensor-core GEMM on pre-split bf16: C = act(A@B^T + bias)
// A[m][128] hi/lo, B[n][128] hi/lo (transposed weights). CTA 256 thr, tile
// 128x64, warp 32x32 (fragment code identical to the R14-validated kernel).
// act=1: silu, output split bf16 (Chh/Chl, stride 128). act=0: fp32 C.
// ---------------------------------------------------------------------------
__global__ __launch_bounds__(256) void hgemm_kernel(
    const __nv_bfloat16* __restrict__ Agh, const __nv_bfloat16* __restrict__ Agl,
    const __nv_bfloat16* __restrict__ Bgh, const __nv_bfloat16* __restrict__ Bgl,
    const float* __restrict__ bias,
    float* __restrict__ Cf,
    __nv_bfloat16* __restrict__ Chh, __nv_bfloat16* __restrict__ Chl,
    int M, int N, int act)
{
    __shared__ __nv_bfloat16 Ah[128][40], Al[128][40];   // 80B rows (16B-mult)
    __shared__ __nv_bfloat16 Bh[64][40],  Bl[64][40];

    const int tid  = threadIdx.x;
    const int warp = tid >> 5;
    const int l    = tid & 31;
    const int gr   = l >> 2;
    const int tg   = l & 3;
    const int wm   = (warp >> 1) * 32;   // 0,32,64,96
    const int wn   = (warp & 1) * 32;    // 0,32
    const int row0 = blockIdx.x * 128;
    const int col0 = blockIdx.y * 64;

    float acc[2][4][4];
    #pragma unroll
    for (int t = 0; t < 2; t++)
        #pragma unroll
        for (int u = 0; u < 4; u++)
            #pragma unroll
            for (int v = 0; v < 4; v++) acc[t][u][v] = 0.0f;

    const uint4 Z = make_uint4(0, 0, 0, 0);

    for (int kc = 0; kc < GK; kc += 32) {
        // ---- stage A 128x32 hi/lo: 512 uint4 each, 2 per thread ----
        #pragma unroll
        for (int s = 0; s < 2; s++) {
            int f  = tid + s * 256;
            int r  = f >> 2;
            int sg = (f & 3) * 8;            // 8 bf16 = 16B segment
            uint4 vh = Z, vl = Z;
            if (row0 + r < M) {
                vh = *(const uint4*)&Agh[(size_t)(row0 + r) * GK + kc + sg];
                vl = *(const uint4*)&Agl[(size_t)(row0 + r) * GK + kc + sg];
            }
            *(uint4*)&Ah[r][sg] = vh;
            *(uint4*)&Al[r][sg] = vl;
        }
        // ---- stage B 64x32 hi/lo: 256 uint4 each, 1 per thread ----
        {
            int r  = tid >> 2;
            int sg = (tid & 3) * 8;
            uint4 vh = *(const uint4*)&Bgh[(size_t)(col0 + r) * GK + kc + sg];
            uint4 vl = *(const uint4*)&Bgl[(size_t)(col0 + r) * GK + kc + sg];
            *(uint4*)&Bh[r][sg] = vh;
            *(uint4*)&Bl[r][sg] = vl;
        }
        __syncthreads();

        #pragma unroll
        for (int ss = 0; ss < 2; ss++) {
            const int kb = ss * 16;
            uint32_t ah[2][4], al[2][4], bh[4][2], bl[4][2];
            #pragma unroll
            for (int t = 0; t < 2; t++) {
                int r1 = wm + t * 16 + gr;
                ah[t][0] = *(const uint32_t*)&Ah[r1    ][kb + tg * 2    ];
                ah[t][1] = *(const uint32_t*)&Ah[r1 + 8][kb + tg * 2    ];
                ah[t][2] = *(const uint32_t*)&Ah[r1    ][kb + tg * 2 + 8];
                ah[t][3] = *(const uint32_t*)&Ah[r1 + 8][kb + tg * 2 + 8];
                al[t][0] = *(const uint32_t*)&Al[r1    ][kb + tg * 2    ];
                al[t][1] = *(const uint32_t*)&Al[r1 + 8][kb + tg * 2    ];
                al[t][2] = *(const uint32_t*)&Al[r1    ][kb + tg * 2 + 8];
                al[t][3] = *(const uint32_t*)&Al[r1 + 8][kb + tg * 2 + 8];
            }
            #pragma unroll
            for (int u = 0; u < 4; u++) {
                int n1 = wn + u * 8 + gr;
                bh[u][0] = *(const uint32_t*)&Bh[n1][kb + tg * 2    ];
                bh[u][1] = *(const uint32_t*)&Bh[n1][kb + tg * 2 + 8];
                bl[u][0] = *(const uint32_t*)&Bl[n1][kb + tg * 2    ];
                bl[u][1] = *(const uint32_t*)&Bl[n1][kb + tg * 2 + 8];
            }
            #pragma unroll
            for (int t = 0; t < 2; t++)
                #pragma unroll
                for (int u = 0; u < 4; u++) {
                    mma_bf16(acc[t][u], ah[t], bh[u]);
                    mma_bf16(acc[t][u], ah[t], bl[u]);
                    mma_bf16(acc[t][u], al[t], bh[u]);
                }
        }
        __syncthreads();
    }

    // ---- epilogue ----
    #pragma unroll
    for (int t = 0; t < 2; t++) {
        #pragma unroll
        for (int u = 0; u < 4; u++) {
            int colg = col0 + wn + u * 8 + tg * 2;
            float b0 = bias[colg], b1 = bias[colg + 1];
            #pragma unroll
            for (int half = 0; half < 2; half++) {
                int rowg = row0 + wm + t * 16 + gr + half * 8;
                if (rowg >= M) continue;
                float x0 = acc[t][u][half * 2 + 0] + b0;
                float x1 = acc[t][u][half * 2 + 1] + b1;
                if (act) {
                    x0 = x0 / (1.0f + expf(-x0));
                    x1 = x1 / (1.0f + expf(-x1));
                    __nv_bfloat16 h0, l0, h1, l1;
                    split_bf(x0, h0, l0);
                    split_bf(x1, h1, l1);
                    *(__nv_bfloat162*)&Chh[(size_t)rowg * GK + colg] = __nv_bfloat162(h0, h1);
                    *(__nv_bfloat162*)&Chl[(size_t)rowg * GK + colg] = __nv_bfloat162(l0, l1);
                } else {
                    *(float2*)&Cf[(size_t)rowg * N + colg] = make_float2(x0, x1);
                }
            }
        }
    }
}

// ---------------------------------------------------------------------------
// Edge kernel (R12 exact — measured 172.7-178us):
// ---------------------------------------------------------------------------
#define ETILE 192

__global__ __launch_bounds__(192) void edge_kernel(
    const float* __restrict__ dist,
    const int* __restrict__ nb,
    const float* __restrict__ Wr,
    const float* __restrict__ br,
    const float* __restrict__ inv,
    float* __restrict__ out,
    int n_edges)
{
    __shared__ __align__(16) float  sm_s[ETILE][NRBF];
    __shared__ __align__(16) float4 sm_meta[ETILE];

    const int t  = threadIdx.x;
    const int c0 = t * 2;
    const int is64 = g_nbrs_is64;

    unsigned long long wrA[NRBF / 2];
    unsigned long long wrB[NRBF / 2];
    #pragma unroll
    for (int m = 0; m < NRBF / 2; m++) {
        float2 we = *(const float2*)&Wr[(2 * m)     * FEAT3 + c0];
        float2 wo = *(const float2*)&Wr[(2 * m + 1) * FEAT3 + c0];
        wrA[m] = pack2(we.x, wo.x);
        wrB[m] = pack2(we.y, wo.y);
    }
    const float2 brp = *(const float2*)&br[c0];

    const int base = blockIdx.x * ETILE;
    const int cnt  = min(ETILE, n_edges - base);

    if (t < cnt) {
        const int e = base + t;
        const float d  = dist[e];
        const float th = d * 0.6283185307179586f;
        const float s1 = sinf(th);
        const float c1 = cosf(th);
        const float env = (d < 5.0f) ? 0.5f * (c1 + 1.0f) : 0.0f;
        const int   j   = is64 ? nb[4 * (long long)e + 2] : nb[2 * (long long)e + 1];
        sm_meta[t] = make_float4(env / d, env, __int_as_float(j), 0.0f);
        const float u = 2.0f * c1;
        float s[NRBF];
        float sp = 0.0f, sc = s1;
        #pragma unroll
        for (int n = 0; n < NRBF; n++) {
            s[n] = sc;
            float sn = fmaf(u, sc, -sp);
            sp = sc; sc = sn;
        }
        #pragma unroll
        for (int q = 0; q < NRBF / 4; q++)
            *(float4*)&sm_s[t][4 * q] =
                make_float4(s[4 * q], s[4 * q + 1], s[4 * q + 2], s[4 * q + 3]);
    }
    __syncthreads();

    float4 meta = sm_meta[0];
    float2 ph   = *(const float2*)&inv[(size_t)__float_as_int(meta.z) * FEAT3 + c0];

    for (int i = 0; i < cnt; i++) {
        const int inext = (i + 1 < cnt) ? (i + 1) : i;
        float4 meta_n = sm_meta[inext];
        float2 ph_n   = *(const float2*)&inv[(size_t)__float_as_int(meta_n.z) * FEAT3 + c0];

        const ulonglong2* sr = (const ulonglong2*)sm_s[i];

        unsigned long long a0e = 0ull, a0o = 0ull, a1e = 0ull, a1o = 0ull;
        #pragma unroll
        for (int q = 0; q < NRBF / 4; q++) {
            ulonglong2 sv = sr[q];
            fma2(a0e, sv.x, wrA[2 * q]);
            fma2(a1e, sv.x, wrB[2 * q]);
            fma2(a0o, sv.y, wrA[2 * q + 1]);
            fma2(a1o, sv.y, wrB[2 * q + 1]);
        }
        float xe0, xo0, xe1, xo1, ye0, yo0, ye1, yo1;
        unpack2(a0e, xe0, xo0); unpack2(a0o, xe1, xo1);
        unpack2(a1e, ye0, yo0); unpack2(a1o, ye1, yo1);
        const float dx = (xe0 + xo0) + (xe1 + xo1);
        const float dy = (ye0 + yo0) + (ye1 + yo1);

        const float wx = fmaf(dx, meta.x, brp.x * meta.y);
        const float wy = fmaf(dy, meta.x, brp.y * meta.y);
        float2 o = make_float2(wx * ph.x, wy * ph.y);
        *(float2*)&out[(size_t)(base + i) * FEAT3 + c0] = o;

        meta = meta_n;
        ph   = ph_n;
    }
}

// ---------------------------------------------------------------------------
// kernel_launch
// ---------------------------------------------------------------------------
extern "C" void kernel_launch(void* const* d_in, const int* in_sizes, int n_in,
                              void* d_out, int out_size)
{
    const float* s_j  = (const float*)d_in[0];
    const float* dist = (const float*)d_in[1];
    const int*   nb   = (const int*)  d_in[2];
    const float* W1   = (const float*)d_in[3];
    const float* b1   = (const float*)d_in[4];
    const float* W2   = (const float*)d_in[5];
    const float* b2   = (const float*)d_in[6];
    const float* Wr   = (const float*)d_in[7];
    const float* br   = (const float*)d_in[8];
    float*       out  = (float*)d_out;

    const int n_nodes = in_sizes[0] / FEAT;
    const int n_edges = in_sizes[1];

    __nv_bfloat16 *sh, *sl, *hh, *hl, *w1h, *w1l, *w2h, *w2l;
    float* invbuf;
    cudaGetSymbolAddress((void**)&sh,  g_sh);
    cudaGetSymbolAddress((void**)&sl,  g_sl);
    cudaGetSymbolAddress((void**)&hh,  g_hh);
    cudaGetSymbolAddress((void**)&hl,  g_hl);
    cudaGetSymbolAddress((void**)&w1h, g_w1h);
    cudaGetSymbolAddress((void**)&w1l, g_w1l);
    cudaGetSymbolAddress((void**)&w2h, g_w2h);
    cudaGetSymbolAddress((void**)&w2l, g_w2l);
    cudaGetSymbolAddress((void**)&invbuf, g_inv);

    detect_nbrs_kernel<<<1, 32>>>((const unsigned int*)nb, in_sizes[2]);

    // pre-split inputs and weights
    {
        int n4 = (n_nodes * FEAT) / 4;
        split_f32_kernel<<<(n4 + 255) / 256, 256>>>((const float4*)s_j, sh, sl, n4);
        int nw = FEAT * FEAT + FEAT3 * FEAT;
        split_w_kernel<<<(nw + 255) / 256, 256>>>(W1, W2);
    }
    // GEMM1: h = silu(s_j @ W1 + b1) -> split bf16 h
    {
        dim3 grid((n_nodes + 127) / 128, FEAT / 64);
        hgemm_kernel<<<grid, 256>>>(sh, sl, w1h, w1l, b1,
                                    nullptr, hh, hl, n_nodes, FEAT, /*act=*/1);
    }
    // GEMM2: inv = h @ W2 + b2 -> fp32
    {
        dim3 grid((n_nodes + 127) / 128, FEAT3 / 64);
        hgemm_kernel<<<grid, 256>>>(hh, hl, w2h, w2l, b2,
                                    invbuf, nullptr, nullptr, n_nodes, FEAT3, /*act=*/0);
    }
    // Edge kernel (unchanged, measured)
    {
        dim3 grid((n_edges + ETILE - 1) / ETILE);
        edge_kernel<<<grid, ETILE>>>(dist, nb, Wr, br, invbuf, out, n_edges);
    }
}